// round 4
// baseline (speedup 1.0000x reference)
#include <cuda_runtime.h>
#include <cstdint>

#define CSc 20
#define NN  14196
#define NTOT (160LL*3LL*14196LL)  // 6,814,080
#define N4 3549                   // NN/4 float4s per conf row
#define DENSE_BLOCKS 960          // 2 blocks per (b,a) conf row
#define NBLOCKS (DENSE_BLOCKS + 160)

// Accumulators — last block resets them so every graph replay starts clean.
__device__ double g_dacc[8];
// [0]=Sall  [1]=Lx [2]=Ly [3]=Lw [4]=Lh [5]=Lco_obj [6]=Lcls [7]=Ssub
__device__ unsigned long long g_cnt[2]; // [0]=n_obj  [1]=n_masked
__device__ unsigned int g_ticket;

__device__ __forceinline__ float sigmoidf_(float c) {
    return 1.0f / (1.0f + __expf(-c));
}

// exact reference form (sparse path, negligible op count there)
__device__ __forceinline__ float noobj_term(float c) {
    float p = sigmoidf_(c);
    p = fminf(fmaxf(p, 1e-7f), (float)(1.0 - 1e-7));
    return -__logf(1.0f - p);
}

// fast dense form: -log(1-clip(sigmoid(c))) == min(softplus(c), -log(1-fl(1-1e-7)))
// cap = -log(1.1920928955e-7) = 23*ln2 = 15.9424226f. 2 MUFU instead of 3.
__device__ __forceinline__ float noobj_fast(float c) {
    return fminf(__logf(1.0f + __expf(c)), 15.9424226f);
}

__global__ void __launch_bounds__(256)
fused_kernel(const float* __restrict__ out,
             const float* __restrict__ tgt,
             const float* __restrict__ anc,
             float* __restrict__ outv) {
    const int blk = blockIdx.x;
    const int tid = threadIdx.x;

    __shared__ double sm[8];

    if (blk < DENSE_BLOCKS) {
        // ---------- dense: half of one (b, a) conf row ----------
        int row  = blk >> 1;           // 0..479
        int half = blk & 1;
        int b = row / 3, a = row - 3 * b;
        const float4* __restrict__ p =
            (const float4*)(out + (size_t)(b * 18 + a * 6 + 4) * NN);
        int jbeg = half ? 1775 : 0;
        int jend = half ? N4 : 1775;
        float s = 0.0f;
        for (int j = jbeg + tid; j < jend; j += 256) {
            float4 v = p[j];
            s += noobj_fast(v.x) + noobj_fast(v.y)
               + noobj_fast(v.z) + noobj_fast(v.w);
        }
        double d = (double)s;
        for (int o = 16; o; o >>= 1) d += __shfl_down_sync(0xffffffffu, d, o);
        if ((tid & 31) == 0) sm[tid >> 5] = d;
        __syncthreads();
        if (tid == 0) {
            double t = 0.0;
            #pragma unroll
            for (int w = 0; w < 8; w++) t += sm[w];
            atomicAdd(&g_dacc[0], t);
        }
    } else {
        // ---------- sparse: one image ----------
        int b  = blk - DENSE_BLOCKS;   // 0..159  (= bs*CS + cs)
        int bs = b / CSc;
        int cs = b - bs * CSc;

        __shared__ float stb[250];
        __shared__ float sanc[18];
        __shared__ int   s_loc[50];
        __shared__ int   s_best[50];
        __shared__ int   s_mask[50];

        for (int i = tid; i < 250; i += 256) stb[i] = tgt[b * 250 + i];
        if (tid < 18) sanc[tid] = anc[tid];
        __syncthreads();

        float Lx = 0.f, Ly = 0.f, Lw = 0.f, Lh = 0.f, Lco = 0.f, Lcls = 0.f, Ssub = 0.f;
        int nobj = 0, nsub = 0;

        const int fws[3] = {26, 52, 104};
        const int n0s[3] = {0, 676, 3380};

        for (int s = 0; s < 3; s++) {
            const int fw = fws[s], n0 = n0s[s];
            float gx = 0.f, gy = 0.f, gw = 0.f, gh = 0.f;
            int best = 0, mask = 0, loc = 0;
            bool valid = false;

            if (tid < 50) {
                float cx = stb[5 * tid + 1];
                float cy = stb[5 * tid + 2];
                float w  = stb[5 * tid + 3];
                float h  = stb[5 * tid + 4];
                valid = (w > 0.0f);
                gx = cx * (float)fw;
                gy = cy * (float)fw;     // square grids
                gw = w * 832.0f;
                gh = h * 832.0f;
                float bi = -1.0f;
                for (int a = 0; a < 3; a++) {
                    float aw = sanc[6 * s + 2 * a];
                    float ah = sanc[6 * s + 2 * a + 1];
                    float inter = fminf(gw, aw) * fminf(gh, ah);
                    float iou   = inter / (gw * gh + aw * ah - inter);
                    if (iou > bi) { bi = iou; best = a; }
                    if (iou > 0.5f) mask |= (1 << a);
                }
                mask |= (1 << best);
                int gi = (int)gx, gj = (int)gy;
                loc = gj * fw + gi;
                if (!valid) mask = 0;
                s_loc[tid]  = loc;
                s_best[tid] = valid ? best : -1;
                s_mask[tid] = mask;
            }
            __syncthreads();

            if (tid < 50 && valid) {
                int prior = 0;
                bool winner = true;
                for (int t2 = 0; t2 < 50; t2++) {
                    if (t2 == tid || s_mask[t2] == 0) continue;
                    if (s_loc[t2] == loc) {
                        if (t2 < tid) prior |= s_mask[t2];
                        else if (s_best[t2] == best) winner = false; // later box wins dup
                    }
                }
                int owned = mask & ~prior;
                for (int a = 0; a < 3; a++) {
                    if ((owned >> a) & 1) {
                        float c = out[(size_t)(b * 18 + a * 6 + 4) * NN + (n0 + loc)];
                        Ssub += noobj_term(c);
                        nsub++;
                    }
                }
                if (winner) {
                    int n = n0 + loc;
                    size_t base = (size_t)(b * 18 + best * 6) * NN + n;
                    float xv = out[base];
                    float yv = out[base + (size_t)NN];
                    float wv = out[base + 2 * (size_t)NN];
                    float hv = out[base + 3 * (size_t)NN];
                    float cv = out[base + 4 * (size_t)NN];
                    float x  = sigmoidf_(xv);
                    float y  = sigmoidf_(yv);
                    float tx = gx - floorf(gx);
                    float ty = gy - floorf(gy);
                    float aw = sanc[6 * s + 2 * best];
                    float ah = sanc[6 * s + 2 * best + 1];
                    float tw = __logf(fmaxf(gw / aw, 1e-7f));
                    float th = __logf(fmaxf(gh / ah, 1e-7f));
                    Lx += (x - tx) * (x - tx);
                    Ly += (y - ty) * (y - ty);
                    Lw += (wv - tw) * (wv - tw);
                    Lh += (hv - th) * (hv - th);
                    float p = fminf(fmaxf(sigmoidf_(cv), 1e-7f), (float)(1.0 - 1e-7));
                    Lco += -__logf(p);
                    nobj++;
                    // class loss: log-softmax over the 20 CS slots at (bs,*,best,n)
                    float l[20];
                    float mx = -1e30f;
                    for (int c = 0; c < 20; c++) {
                        l[c] = out[(size_t)((bs * 20 + c) * 18 + best * 6 + 5) * NN + n];
                        mx = fmaxf(mx, l[c]);
                    }
                    float se = 0.0f;
                    for (int c = 0; c < 20; c++) se += __expf(l[c] - mx);
                    float lse = mx + __logf(se);
                    Lcls += lse - l[cs];
                }
            }
            __syncthreads();
        }

        // block reduce 7 doubles + 2 ints
        float vals[7] = {Lx, Ly, Lw, Lh, Lco, Lcls, Ssub};
        #pragma unroll
        for (int i = 0; i < 7; i++) {
            double d = (double)vals[i];
            for (int o = 16; o; o >>= 1) d += __shfl_down_sync(0xffffffffu, d, o);
            if ((tid & 31) == 0) sm[tid >> 5] = d;
            __syncthreads();
            if (tid == 0) {
                double t = 0.0;
                #pragma unroll
                for (int w = 0; w < 8; w++) t += sm[w];
                atomicAdd(&g_dacc[1 + i], t);
            }
            __syncthreads();
        }
        __shared__ int ism[8];
        int iv[2] = {nobj, nsub};
        #pragma unroll
        for (int i = 0; i < 2; i++) {
            int d = iv[i];
            for (int o = 16; o; o >>= 1) d += __shfl_down_sync(0xffffffffu, d, o);
            if ((tid & 31) == 0) ism[tid >> 5] = d;
            __syncthreads();
            if (tid == 0) {
                int t = 0;
                #pragma unroll
                for (int w = 0; w < 8; w++) t += ism[w];
                atomicAdd(&g_cnt[i], (unsigned long long)t);
            }
            __syncthreads();
        }
    }

    // ---------- last-block finalize + reset ----------
    if (tid == 0) {
        __threadfence();
        unsigned int ticket = atomicAdd(&g_ticket, 1u);
        if (ticket == NBLOCKS - 1) {
            __threadfence();
            double nobj = (double)g_cnt[0];
            if (nobj < 1.0) nobj = 1.0;
            double nno = (double)(NTOT - (long long)g_cnt[1]);
            if (nno < 1.0) nno = 1.0;
            double loss = (g_dacc[1] + g_dacc[2] + g_dacc[3] + g_dacc[4]) / nobj
                        + g_dacc[5] / nobj
                        + 100.0 * (g_dacc[0] - g_dacc[7]) / nno
                        + g_dacc[6] / nobj;
            outv[0] = (float)loss;
            // reset for next replay
            #pragma unroll
            for (int i = 0; i < 8; i++) g_dacc[i] = 0.0;
            g_cnt[0] = 0ULL;
            g_cnt[1] = 0ULL;
            g_ticket = 0u;
        }
    }
}

extern "C" void kernel_launch(void* const* d_in, const int* in_sizes, int n_in,
                              void* d_out, int out_size) {
    const float* output  = (const float*)d_in[0];
    const float* target  = (const float*)d_in[1];
    const float* anchors = (const float*)d_in[2];
    fused_kernel<<<NBLOCKS, 256>>>(output, target, anchors, (float*)d_out);
}

// round 5
// speedup vs baseline: 1.4369x; 1.4369x over previous
#include <cuda_runtime.h>
#include <cstdint>

#define CSc 20
#define NN  14196
#define NTOT (160LL*3LL*14196LL)  // 6,814,080
#define N4 3549                   // NN/4 float4s per conf row
#define NBLOCKS 592               // 4 blocks/SM on 148 SMs — exactly one wave
#define NUNITS 1920               // 480 rows x 4 quarter-units of 1024 float4

// Accumulators — last block resets them so every graph replay starts clean.
__device__ double g_dacc[8];
// [0]=Sall  [1]=Lx [2]=Ly [3]=Lw [4]=Lh [5]=Lco_obj [6]=Lcls [7]=Ssub
__device__ unsigned long long g_cnt[2]; // [0]=n_obj  [1]=n_masked
__device__ unsigned int g_ticket;

__device__ __forceinline__ float sigmoidf_(float c) {
    return 1.0f / (1.0f + __expf(-c));
}

// exact reference form (sparse path only)
__device__ __forceinline__ float noobj_term(float c) {
    float p = sigmoidf_(c);
    p = fminf(fmaxf(p, 1e-7f), (float)(1.0 - 1e-7));
    return -__logf(1.0f - p);
}

// dense form: -log(1-clip(sigmoid(c))) == min(softplus(c), 15.9424226)
// noobj_fast(-88) == 0 exactly -> sentinel for predicated-off lanes.
__device__ __forceinline__ float noobj_fast(float c) {
    return fminf(__logf(1.0f + __expf(c)), 15.9424226f);
}

__global__ void __launch_bounds__(256)
fused_kernel(const float* __restrict__ out,
             const float* __restrict__ tgt,
             const float* __restrict__ anc,
             float* __restrict__ outv) {
    const int blk = blockIdx.x;
    const int tid = threadIdx.x;

    __shared__ double sm[8];

    // ================= sparse first (blocks 0..159), overlaps dense =========
    if (blk < 160) {
        int b  = blk;            // 0..159  (= bs*CS + cs)
        int bs = b / CSc;
        int cs = b - bs * CSc;

        __shared__ float stb[250];
        __shared__ float sanc[18];
        __shared__ int   s_loc[50];
        __shared__ int   s_best[50];
        __shared__ int   s_mask[50];

        for (int i = tid; i < 250; i += 256) stb[i] = tgt[b * 250 + i];
        if (tid < 18) sanc[tid] = anc[tid];
        __syncthreads();

        float Lx = 0.f, Ly = 0.f, Lw = 0.f, Lh = 0.f, Lco = 0.f, Lcls = 0.f, Ssub = 0.f;
        int nobj = 0, nsub = 0;

        const int fws[3] = {26, 52, 104};
        const int n0s[3] = {0, 676, 3380};

        for (int s = 0; s < 3; s++) {
            const int fw = fws[s], n0 = n0s[s];
            float gx = 0.f, gy = 0.f, gw = 0.f, gh = 0.f;
            int best = 0, mask = 0, loc = 0;
            bool valid = false;

            if (tid < 50) {
                float cx = stb[5 * tid + 1];
                float cy = stb[5 * tid + 2];
                float w  = stb[5 * tid + 3];
                float h  = stb[5 * tid + 4];
                valid = (w > 0.0f);
                gx = cx * (float)fw;
                gy = cy * (float)fw;
                gw = w * 832.0f;
                gh = h * 832.0f;
                float bi = -1.0f;
                for (int a = 0; a < 3; a++) {
                    float aw = sanc[6 * s + 2 * a];
                    float ah = sanc[6 * s + 2 * a + 1];
                    float inter = fminf(gw, aw) * fminf(gh, ah);
                    float iou   = inter / (gw * gh + aw * ah - inter);
                    if (iou > bi) { bi = iou; best = a; }
                    if (iou > 0.5f) mask |= (1 << a);
                }
                mask |= (1 << best);
                int gi = (int)gx, gj = (int)gy;
                loc = gj * fw + gi;
                if (!valid) mask = 0;
                s_loc[tid]  = loc;
                s_best[tid] = valid ? best : -1;
                s_mask[tid] = mask;
            }
            __syncthreads();

            if (tid < 50 && valid) {
                int prior = 0;
                bool winner = true;
                for (int t2 = 0; t2 < 50; t2++) {
                    if (t2 == tid || s_mask[t2] == 0) continue;
                    if (s_loc[t2] == loc) {
                        if (t2 < tid) prior |= s_mask[t2];
                        else if (s_best[t2] == best) winner = false;
                    }
                }
                int owned = mask & ~prior;
                for (int a = 0; a < 3; a++) {
                    if ((owned >> a) & 1) {
                        float c = out[(size_t)(b * 18 + a * 6 + 4) * NN + (n0 + loc)];
                        Ssub += noobj_term(c);
                        nsub++;
                    }
                }
                if (winner) {
                    int n = n0 + loc;
                    size_t base = (size_t)(b * 18 + best * 6) * NN + n;
                    float xv = out[base];
                    float yv = out[base + (size_t)NN];
                    float wv = out[base + 2 * (size_t)NN];
                    float hv = out[base + 3 * (size_t)NN];
                    float cv = out[base + 4 * (size_t)NN];
                    float x  = sigmoidf_(xv);
                    float y  = sigmoidf_(yv);
                    float tx = gx - floorf(gx);
                    float ty = gy - floorf(gy);
                    float aw = sanc[6 * s + 2 * best];
                    float ah = sanc[6 * s + 2 * best + 1];
                    float tw = __logf(fmaxf(gw / aw, 1e-7f));
                    float th = __logf(fmaxf(gh / ah, 1e-7f));
                    Lx += (x - tx) * (x - tx);
                    Ly += (y - ty) * (y - ty);
                    Lw += (wv - tw) * (wv - tw);
                    Lh += (hv - th) * (hv - th);
                    float p = fminf(fmaxf(sigmoidf_(cv), 1e-7f), (float)(1.0 - 1e-7));
                    Lco += -__logf(p);
                    nobj++;
                    float l[20];
                    float mx = -1e30f;
                    #pragma unroll
                    for (int c = 0; c < 20; c++) {
                        l[c] = out[(size_t)((bs * 20 + c) * 18 + best * 6 + 5) * NN + n];
                        mx = fmaxf(mx, l[c]);
                    }
                    float se = 0.0f;
                    #pragma unroll
                    for (int c = 0; c < 20; c++) se += __expf(l[c] - mx);
                    float lse = mx + __logf(se);
                    Lcls += lse - l[cs];
                }
            }
            __syncthreads();
        }

        // block reduce 7 doubles + 2 ints
        float vals[7] = {Lx, Ly, Lw, Lh, Lco, Lcls, Ssub};
        #pragma unroll
        for (int i = 0; i < 7; i++) {
            double d = (double)vals[i];
            for (int o = 16; o; o >>= 1) d += __shfl_down_sync(0xffffffffu, d, o);
            if ((tid & 31) == 0) sm[tid >> 5] = d;
            __syncthreads();
            if (tid == 0) {
                double t = 0.0;
                #pragma unroll
                for (int w = 0; w < 8; w++) t += sm[w];
                atomicAdd(&g_dacc[1 + i], t);
            }
            __syncthreads();
        }
        __shared__ int ism[8];
        int iv[2] = {nobj, nsub};
        #pragma unroll
        for (int i = 0; i < 2; i++) {
            int d = iv[i];
            for (int o = 16; o; o >>= 1) d += __shfl_down_sync(0xffffffffu, d, o);
            if ((tid & 31) == 0) ism[tid >> 5] = d;
            __syncthreads();
            if (tid == 0) {
                int t = 0;
                #pragma unroll
                for (int w = 0; w < 8; w++) t += ism[w];
                atomicAdd(&g_cnt[i], (unsigned long long)t);
            }
            __syncthreads();
        }
    }

    // ================= dense: all blocks pull quarter-row units =============
    // unit u: row = u>>2 (0..479), quarter q = u&3 covers float4 [q*1024, ...).
    // Reversed assignment so blocks without sparse work take the extra units.
    {
        float s = 0.0f;
        for (int u = (NBLOCKS - 1) - blk; u < NUNITS; u += NBLOCKS) {
            int row = u >> 2, q = u & 3;
            int b = row / 3, a = row - 3 * b;
            const float4* __restrict__ p =
                (const float4*)(out + (size_t)(b * 18 + a * 6 + 4) * NN);
            int j = q * 1024 + tid;
            const float4 SENT = make_float4(-88.f, -88.f, -88.f, -88.f);
            // 4 independent predicated loads -> MLP=4
            float4 v0 = (j          < N4) ? p[j]       : SENT;
            float4 v1 = (j + 256    < N4) ? p[j + 256] : SENT;
            float4 v2 = (j + 512    < N4) ? p[j + 512] : SENT;
            float4 v3 = (j + 768    < N4) ? p[j + 768] : SENT;
            s += noobj_fast(v0.x) + noobj_fast(v0.y) + noobj_fast(v0.z) + noobj_fast(v0.w);
            s += noobj_fast(v1.x) + noobj_fast(v1.y) + noobj_fast(v1.z) + noobj_fast(v1.w);
            s += noobj_fast(v2.x) + noobj_fast(v2.y) + noobj_fast(v2.z) + noobj_fast(v2.w);
            s += noobj_fast(v3.x) + noobj_fast(v3.y) + noobj_fast(v3.z) + noobj_fast(v3.w);
        }
        double d = (double)s;
        for (int o = 16; o; o >>= 1) d += __shfl_down_sync(0xffffffffu, d, o);
        __syncthreads();   // sm[] reuse safe (sparse path done with it)
        if ((tid & 31) == 0) sm[tid >> 5] = d;
        __syncthreads();
        if (tid == 0) {
            double t = 0.0;
            #pragma unroll
            for (int w = 0; w < 8; w++) t += sm[w];
            atomicAdd(&g_dacc[0], t);
        }
    }

    // ================= last-block finalize + reset ==========================
    if (tid == 0) {
        __threadfence();
        unsigned int ticket = atomicAdd(&g_ticket, 1u);
        if (ticket == NBLOCKS - 1) {
            __threadfence();
            double nobj = (double)g_cnt[0];
            if (nobj < 1.0) nobj = 1.0;
            double nno = (double)(NTOT - (long long)g_cnt[1]);
            if (nno < 1.0) nno = 1.0;
            double loss = (g_dacc[1] + g_dacc[2] + g_dacc[3] + g_dacc[4]) / nobj
                        + g_dacc[5] / nobj
                        + 100.0 * (g_dacc[0] - g_dacc[7]) / nno
                        + g_dacc[6] / nobj;
            outv[0] = (float)loss;
            #pragma unroll
            for (int i = 0; i < 8; i++) g_dacc[i] = 0.0;
            g_cnt[0] = 0ULL;
            g_cnt[1] = 0ULL;
            g_ticket = 0u;
        }
    }
}

extern "C" void kernel_launch(void* const* d_in, const int* in_sizes, int n_in,
                              void* d_out, int out_size) {
    const float* output  = (const float*)d_in[0];
    const float* target  = (const float*)d_in[1];
    const float* anchors = (const float*)d_in[2];
    fused_kernel<<<NBLOCKS, 256>>>(output, target, anchors, (float*)d_out);
}

// round 6
// speedup vs baseline: 2.0187x; 1.4049x over previous
#include <cuda_runtime.h>
#include <cstdint>

#define CSc 20
#define NN  14196
#define NTOT (160LL*3LL*14196LL)  // 6,814,080
#define N4 3549                   // NN/4 float4s per conf row
#define NBLOCKS 592               // 4 blocks/SM on 148 SMs — one wave
#define NUNITS 1920               // 480 rows x 4 quarter-units of 1024 float4

// Accumulators — last block resets them so every graph replay starts clean.
__device__ double g_dacc[8];
// [0]=Sall  [1]=Lx [2]=Ly [3]=Lw [4]=Lh [5]=Lco_obj [6]=Lcls [7]=Ssub
__device__ unsigned long long g_cnt[2]; // [0]=n_obj  [1]=n_masked
__device__ unsigned int g_ticket;

__device__ __forceinline__ float sigmoidf_(float c) {
    return 1.0f / (1.0f + __expf(-c));
}

// exact reference form (sparse path only)
__device__ __forceinline__ float noobj_term(float c) {
    float p = sigmoidf_(c);
    p = fminf(fmaxf(p, 1e-7f), (float)(1.0 - 1e-7));
    return -__logf(1.0f - p);
}

// dense form: -log(1-clip(sigmoid(c))) == min(softplus(c), 15.9424226)
// noobj_fast(-88) == 0 exactly -> sentinel for predicated-off lanes.
__device__ __forceinline__ float noobj_fast(float c) {
    return fminf(__logf(1.0f + __expf(c)), 15.9424226f);
}

__global__ void __launch_bounds__(256, 4)
fused_kernel(const float* __restrict__ out,
             const float* __restrict__ tgt,
             const float* __restrict__ anc,
             float* __restrict__ outv) {
    const int blk = blockIdx.x;
    const int tid = threadIdx.x;

    __shared__ double sm[8];

    float Lx = 0.f, Ly = 0.f, Lw = 0.f, Lh = 0.f, Lco = 0.f, Lcls = 0.f, Ssub = 0.f;
    int nobj = 0, nsub = 0;

    // ========== sparse (blocks 0..159): one image, (scale,box)->thread ======
    if (blk < 160) {
        int b  = blk;            // = bs*CS + cs
        int bs = b / CSc;
        int cs = b - bs * CSc;

        __shared__ float stb[250];
        __shared__ float sanc[18];
        __shared__ short s_loc[150];
        __shared__ signed char s_best[150];
        __shared__ signed char s_mask[150];

        for (int i = tid; i < 250; i += 256) stb[i] = tgt[b * 250 + i];
        if (tid < 18) sanc[tid] = anc[tid];
        __syncthreads();

        // phase 1: per-unit metadata (150 units = 3 scales x 50 boxes)
        int sca = tid / 50;                 // valid when tid<150
        int box = tid - sca * 50;
        int fw = (sca == 0) ? 26 : (sca == 1) ? 52 : 104;
        int n0 = (sca == 0) ? 0  : (sca == 1) ? 676 : 3380;

        float gx = 0.f, gy = 0.f, gw = 0.f, gh = 0.f;
        int best = 0, mask = 0, loc = 0;
        bool valid = false;

        if (tid < 150) {
            float cx = stb[5 * box + 1];
            float cy = stb[5 * box + 2];
            float w  = stb[5 * box + 3];
            float h  = stb[5 * box + 4];
            valid = (w > 0.0f);
            gx = cx * (float)fw;
            gy = cy * (float)fw;            // square grids
            gw = w * 832.0f;
            gh = h * 832.0f;
            float bi = -1.0f;
            #pragma unroll
            for (int a = 0; a < 3; a++) {
                float aw = sanc[6 * sca + 2 * a];
                float ah = sanc[6 * sca + 2 * a + 1];
                float inter = fminf(gw, aw) * fminf(gh, ah);
                float iou   = inter / (gw * gh + aw * ah - inter);
                if (iou > bi) { bi = iou; best = a; }
                if (iou > 0.5f) mask |= (1 << a);
            }
            mask |= (1 << best);
            int gi = (int)gx, gj = (int)gy;
            loc = gj * fw + gi;
            if (!valid) mask = 0;
            s_loc[tid]  = (short)loc;
            s_best[tid] = (signed char)(valid ? best : -1);
            s_mask[tid] = (signed char)mask;
        }
        __syncthreads();

        // phase 2: dedup scan (same-scale range only) + all gathers, 5 warps
        if (tid < 150 && valid) {
            int base0 = sca * 50;
            int prior = 0;
            bool winner = true;
            for (int t2 = base0; t2 < base0 + 50; t2++) {
                if (t2 == tid) continue;
                int m2 = s_mask[t2];
                if (m2 == 0) continue;
                if ((int)s_loc[t2] == loc) {
                    if (t2 < tid) prior |= m2;
                    else if ((int)s_best[t2] == best) winner = false; // later box wins
                }
            }
            int owned = mask & ~prior;
            #pragma unroll
            for (int a = 0; a < 3; a++) {
                if ((owned >> a) & 1) {
                    float c = out[(size_t)(b * 18 + a * 6 + 4) * NN + (n0 + loc)];
                    Ssub += noobj_term(c);
                    nsub++;
                }
            }
            if (winner) {
                int n = n0 + loc;
                size_t base = (size_t)(b * 18 + best * 6) * NN + n;
                float xv = out[base];
                float yv = out[base + (size_t)NN];
                float wv = out[base + 2 * (size_t)NN];
                float hv = out[base + 3 * (size_t)NN];
                float cv = out[base + 4 * (size_t)NN];
                // class logits: 20 independent loads, 1.02MB stride
                float l[20];
                #pragma unroll
                for (int c = 0; c < 20; c++)
                    l[c] = out[(size_t)((bs * 20 + c) * 18 + best * 6 + 5) * NN + n];

                float x  = sigmoidf_(xv);
                float y  = sigmoidf_(yv);
                float tx = gx - floorf(gx);
                float ty = gy - floorf(gy);
                float aw = sanc[6 * sca + 2 * best];
                float ah = sanc[6 * sca + 2 * best + 1];
                float tw = __logf(fmaxf(gw / aw, 1e-7f));
                float th = __logf(fmaxf(gh / ah, 1e-7f));
                Lx += (x - tx) * (x - tx);
                Ly += (y - ty) * (y - ty);
                Lw += (wv - tw) * (wv - tw);
                Lh += (hv - th) * (hv - th);
                float p = fminf(fmaxf(sigmoidf_(cv), 1e-7f), (float)(1.0 - 1e-7));
                Lco += -__logf(p);
                nobj++;

                float mx = l[0];
                #pragma unroll
                for (int c = 1; c < 20; c++) mx = fmaxf(mx, l[c]);
                float se = 0.0f;
                #pragma unroll
                for (int c = 0; c < 20; c++) se += __expf(l[c] - mx);
                Lcls += (mx + __logf(se)) - l[cs];
            }
        }
        __syncthreads();

        // block reduce 7 doubles + 2 ints (inactive threads contribute 0)
        float vals[7] = {Lx, Ly, Lw, Lh, Lco, Lcls, Ssub};
        #pragma unroll
        for (int i = 0; i < 7; i++) {
            double d = (double)vals[i];
            for (int o = 16; o; o >>= 1) d += __shfl_down_sync(0xffffffffu, d, o);
            if ((tid & 31) == 0) sm[tid >> 5] = d;
            __syncthreads();
            if (tid == 0) {
                double t = 0.0;
                #pragma unroll
                for (int w = 0; w < 8; w++) t += sm[w];
                atomicAdd(&g_dacc[1 + i], t);
            }
            __syncthreads();
        }
        __shared__ int ism[8];
        int iv[2] = {nobj, nsub};
        #pragma unroll
        for (int i = 0; i < 2; i++) {
            int d = iv[i];
            for (int o = 16; o; o >>= 1) d += __shfl_down_sync(0xffffffffu, d, o);
            if ((tid & 31) == 0) ism[tid >> 5] = d;
            __syncthreads();
            if (tid == 0) {
                int t = 0;
                #pragma unroll
                for (int w = 0; w < 8; w++) t += ism[w];
                atomicAdd(&g_cnt[i], (unsigned long long)t);
            }
            __syncthreads();
        }
    }

    // ========== dense: all blocks pull quarter-row units ====================
    {
        float s = 0.0f;
        for (int u = (NBLOCKS - 1) - blk; u < NUNITS; u += NBLOCKS) {
            int row = u >> 2, q = u & 3;
            int b = row / 3, a = row - 3 * b;
            const float4* __restrict__ p =
                (const float4*)(out + (size_t)(b * 18 + a * 6 + 4) * NN);
            int j = q * 1024 + tid;
            const float4 SENT = make_float4(-88.f, -88.f, -88.f, -88.f);
            float4 v0 = (j       < N4) ? p[j]       : SENT;
            float4 v1 = (j + 256 < N4) ? p[j + 256] : SENT;
            float4 v2 = (j + 512 < N4) ? p[j + 512] : SENT;
            float4 v3 = (j + 768 < N4) ? p[j + 768] : SENT;
            s += noobj_fast(v0.x) + noobj_fast(v0.y) + noobj_fast(v0.z) + noobj_fast(v0.w);
            s += noobj_fast(v1.x) + noobj_fast(v1.y) + noobj_fast(v1.z) + noobj_fast(v1.w);
            s += noobj_fast(v2.x) + noobj_fast(v2.y) + noobj_fast(v2.z) + noobj_fast(v2.w);
            s += noobj_fast(v3.x) + noobj_fast(v3.y) + noobj_fast(v3.z) + noobj_fast(v3.w);
        }
        double d = (double)s;
        for (int o = 16; o; o >>= 1) d += __shfl_down_sync(0xffffffffu, d, o);
        __syncthreads();   // sm[] reuse safe
        if ((tid & 31) == 0) sm[tid >> 5] = d;
        __syncthreads();
        if (tid == 0) {
            double t = 0.0;
            #pragma unroll
            for (int w = 0; w < 8; w++) t += sm[w];
            atomicAdd(&g_dacc[0], t);
        }
    }

    // ========== last-block finalize + reset =================================
    if (tid == 0) {
        __threadfence();
        unsigned int ticket = atomicAdd(&g_ticket, 1u);
        if (ticket == NBLOCKS - 1) {
            __threadfence();
            double nv = (double)g_cnt[0];
            if (nv < 1.0) nv = 1.0;
            double nno = (double)(NTOT - (long long)g_cnt[1]);
            if (nno < 1.0) nno = 1.0;
            double loss = (g_dacc[1] + g_dacc[2] + g_dacc[3] + g_dacc[4]) / nv
                        + g_dacc[5] / nv
                        + 100.0 * (g_dacc[0] - g_dacc[7]) / nno
                        + g_dacc[6] / nv;
            outv[0] = (float)loss;
            #pragma unroll
            for (int i = 0; i < 8; i++) g_dacc[i] = 0.0;
            g_cnt[0] = 0ULL;
            g_cnt[1] = 0ULL;
            g_ticket = 0u;
        }
    }
}

extern "C" void kernel_launch(void* const* d_in, const int* in_sizes, int n_in,
                              void* d_out, int out_size) {
    const float* output  = (const float*)d_in[0];
    const float* target  = (const float*)d_in[1];
    const float* anchors = (const float*)d_in[2];
    fused_kernel<<<NBLOCKS, 256>>>(output, target, anchors, (float*)d_out);
}

// round 7
// speedup vs baseline: 2.1899x; 1.0848x over previous
#include <cuda_runtime.h>
#include <cstdint>

#define CSc 20
#define NN  14196
#define NTOT (160LL*3LL*14196LL)  // 6,814,080
#define N4 3549                   // NN/4 float4s per conf row
#define NBLOCKS 592               // 4 blocks/SM on 148 SMs — one wave
#define NUNITS 1920               // 480 rows x 4 quarter-units of 1024 float4
#define NSPARSE 480               // (image, scale) pairs

// Accumulators — last block resets them so every graph replay starts clean.
__device__ double g_dacc[4];
// [0]=Sall  [1]=Aobj (Lx+Ly+Lw+Lh+Lco+Lcls)  [2]=Ssub
__device__ unsigned long long g_cnt[2]; // [0]=n_obj  [1]=n_masked
__device__ unsigned int g_ticket;

__device__ __forceinline__ float sigmoidf_(float c) {
    return 1.0f / (1.0f + __expf(-c));
}

// exact reference form (sparse path only)
__device__ __forceinline__ float noobj_term(float c) {
    float p = sigmoidf_(c);
    p = fminf(fmaxf(p, 1e-7f), (float)(1.0 - 1e-7));
    return -__logf(1.0f - p);
}

// dense form: -log(1-clip(sigmoid(c))) == min(softplus(c), 15.9424226)
// noobj_fast(-88) == 0 exactly -> sentinel for predicated-off lanes.
__device__ __forceinline__ float noobj_fast(float c) {
    return fminf(__logf(1.0f + __expf(c)), 15.9424226f);
}

__global__ void __launch_bounds__(256, 4)
fused_kernel(const float* __restrict__ out,
             const float* __restrict__ tgt,
             const float* __restrict__ anc,
             float* __restrict__ outv) {
    const int blk = blockIdx.x;
    const int tid = threadIdx.x;

    __shared__ double sm[8];

    // ========== sparse (blocks 0..479): one (image, scale) ==================
    if (blk < NSPARSE) {
        int b   = blk / 3;             // image 0..159  (= bs*CS + cs)
        int sca = blk - 3 * b;         // scale 0..2
        int bs  = b / CSc;
        int cs  = b - bs * CSc;
        int fw  = (sca == 0) ? 26 : (sca == 1) ? 52 : 104;
        int n0  = (sca == 0) ? 0  : (sca == 1) ? 676 : 3380;

        __shared__ float stb[250];
        __shared__ float sanc[6];
        __shared__ short s_loc[50];
        __shared__ signed char s_best[50];
        __shared__ signed char s_mask[50];

        for (int i = tid; i < 250; i += 256) stb[i] = tgt[b * 250 + i];
        if (tid < 6) sanc[tid] = anc[6 * sca + tid];
        __syncthreads();

        float Aobj = 0.f, Ssub = 0.f;
        int nobj = 0, nsub = 0;

        float gx = 0.f, gy = 0.f, gw = 0.f, gh = 0.f;
        int best = 0, mask = 0, loc = 0;
        bool valid = false;

        if (tid < 50) {
            float cx = stb[5 * tid + 1];
            float cy = stb[5 * tid + 2];
            float w  = stb[5 * tid + 3];
            float h  = stb[5 * tid + 4];
            valid = (w > 0.0f);
            gx = cx * (float)fw;
            gy = cy * (float)fw;       // square grids
            gw = w * 832.0f;
            gh = h * 832.0f;
            float bi = -1.0f;
            #pragma unroll
            for (int a = 0; a < 3; a++) {
                float aw = sanc[2 * a];
                float ah = sanc[2 * a + 1];
                float inter = fminf(gw, aw) * fminf(gh, ah);
                float iou   = inter / (gw * gh + aw * ah - inter);
                if (iou > bi) { bi = iou; best = a; }
                if (iou > 0.5f) mask |= (1 << a);
            }
            mask |= (1 << best);
            int gi = (int)gx, gj = (int)gy;
            loc = gj * fw + gi;
            if (!valid) mask = 0;
            s_loc[tid]  = (short)loc;
            s_best[tid] = (signed char)(valid ? best : -1);
            s_mask[tid] = (signed char)mask;
        }
        __syncthreads();

        if (tid < 50 && valid) {
            // dedup scan (within this scale only — exact reference semantics)
            int prior = 0;
            bool winner = true;
            for (int t2 = 0; t2 < 50; t2++) {
                if (t2 == tid) continue;
                int m2 = s_mask[t2];
                if (m2 == 0) continue;
                if ((int)s_loc[t2] == loc) {
                    if (t2 < tid) prior |= m2;
                    else if ((int)s_best[t2] == best) winner = false; // later box wins
                }
            }
            int owned = mask & ~prior;
            #pragma unroll
            for (int a = 0; a < 3; a++) {
                if ((owned >> a) & 1) {
                    float c = out[(size_t)(b * 18 + a * 6 + 4) * NN + (n0 + loc)];
                    Ssub += noobj_term(c);
                    nsub++;
                }
            }
            if (winner) {
                int n = n0 + loc;
                size_t base = (size_t)(b * 18 + best * 6) * NN + n;
                float xv = out[base];
                float yv = out[base + (size_t)NN];
                float wv = out[base + 2 * (size_t)NN];
                float hv = out[base + 3 * (size_t)NN];
                float cv = out[base + 4 * (size_t)NN];

                // class logits, pass 1: 20 independent loads -> max (+ grab l[cs])
                const float* __restrict__ clsp =
                    out + (size_t)(bs * 20 * 18 + best * 6 + 5) * NN + n;
                const size_t CSTRIDE = (size_t)18 * NN;
                float mx = -1e30f, lcs = 0.0f;
                #pragma unroll
                for (int c = 0; c < 20; c++) {
                    float lc = clsp[c * CSTRIDE];
                    mx = fmaxf(mx, lc);
                    if (c == cs) lcs = lc;
                }
                // pass 2: reload (L1 hits) -> sum of exp
                float se = 0.0f;
                #pragma unroll
                for (int c = 0; c < 20; c++) {
                    float lc = clsp[c * CSTRIDE];
                    se += __expf(lc - mx);
                }

                float x  = sigmoidf_(xv);
                float y  = sigmoidf_(yv);
                float tx = gx - floorf(gx);
                float ty = gy - floorf(gy);
                float aw = sanc[2 * best];
                float ah = sanc[2 * best + 1];
                float tw = __logf(fmaxf(gw / aw, 1e-7f));
                float th = __logf(fmaxf(gh / ah, 1e-7f));
                float p  = fminf(fmaxf(sigmoidf_(cv), 1e-7f), (float)(1.0 - 1e-7));

                Aobj += (x - tx) * (x - tx) + (y - ty) * (y - ty)
                      + (wv - tw) * (wv - tw) + (hv - th) * (hv - th)
                      + (-__logf(p))
                      + (mx + __logf(se)) - lcs;
                nobj++;
            }
        }
        __syncthreads();

        // block reduce: 2 doubles + 2 ints
        float vals[2] = {Aobj, Ssub};
        #pragma unroll
        for (int i = 0; i < 2; i++) {
            double d = (double)vals[i];
            for (int o = 16; o; o >>= 1) d += __shfl_down_sync(0xffffffffu, d, o);
            if ((tid & 31) == 0) sm[tid >> 5] = d;
            __syncthreads();
            if (tid == 0) {
                double t = 0.0;
                #pragma unroll
                for (int w = 0; w < 8; w++) t += sm[w];
                atomicAdd(&g_dacc[1 + i], t);
            }
            __syncthreads();
        }
        __shared__ int ism[8];
        int iv[2] = {nobj, nsub};
        #pragma unroll
        for (int i = 0; i < 2; i++) {
            int d = iv[i];
            for (int o = 16; o; o >>= 1) d += __shfl_down_sync(0xffffffffu, d, o);
            if ((tid & 31) == 0) ism[tid >> 5] = d;
            __syncthreads();
            if (tid == 0) {
                int t = 0;
                #pragma unroll
                for (int w = 0; w < 8; w++) t += ism[w];
                atomicAdd(&g_cnt[i], (unsigned long long)t);
            }
            __syncthreads();
        }
    }

    // ========== dense: all blocks pull quarter-row units ====================
    {
        float s = 0.0f;
        for (int u = (NBLOCKS - 1) - blk; u < NUNITS; u += NBLOCKS) {
            int row = u >> 2, q = u & 3;
            int b = row / 3, a = row - 3 * b;
            const float4* __restrict__ p =
                (const float4*)(out + (size_t)(b * 18 + a * 6 + 4) * NN);
            int j = q * 1024 + tid;
            const float4 SENT = make_float4(-88.f, -88.f, -88.f, -88.f);
            float4 v0 = (j       < N4) ? p[j]       : SENT;
            float4 v1 = (j + 256 < N4) ? p[j + 256] : SENT;
            float4 v2 = (j + 512 < N4) ? p[j + 512] : SENT;
            float4 v3 = (j + 768 < N4) ? p[j + 768] : SENT;
            s += noobj_fast(v0.x) + noobj_fast(v0.y) + noobj_fast(v0.z) + noobj_fast(v0.w);
            s += noobj_fast(v1.x) + noobj_fast(v1.y) + noobj_fast(v1.z) + noobj_fast(v1.w);
            s += noobj_fast(v2.x) + noobj_fast(v2.y) + noobj_fast(v2.z) + noobj_fast(v2.w);
            s += noobj_fast(v3.x) + noobj_fast(v3.y) + noobj_fast(v3.z) + noobj_fast(v3.w);
        }
        double d = (double)s;
        for (int o = 16; o; o >>= 1) d += __shfl_down_sync(0xffffffffu, d, o);
        __syncthreads();   // sm[] reuse safe
        if ((tid & 31) == 0) sm[tid >> 5] = d;
        __syncthreads();
        if (tid == 0) {
            double t = 0.0;
            #pragma unroll
            for (int w = 0; w < 8; w++) t += sm[w];
            atomicAdd(&g_dacc[0], t);
        }
    }

    // ========== last-block finalize + reset =================================
    if (tid == 0) {
        __threadfence();
        unsigned int ticket = atomicAdd(&g_ticket, 1u);
        if (ticket == NBLOCKS - 1) {
            __threadfence();
            double nv = (double)g_cnt[0];
            if (nv < 1.0) nv = 1.0;
            double nno = (double)(NTOT - (long long)g_cnt[1]);
            if (nno < 1.0) nno = 1.0;
            double loss = g_dacc[1] / nv
                        + 100.0 * (g_dacc[0] - g_dacc[2]) / nno;
            outv[0] = (float)loss;
            #pragma unroll
            for (int i = 0; i < 4; i++) g_dacc[i] = 0.0;
            g_cnt[0] = 0ULL;
            g_cnt[1] = 0ULL;
            g_ticket = 0u;
        }
    }
}

extern "C" void kernel_launch(void* const* d_in, const int* in_sizes, int n_in,
                              void* d_out, int out_size) {
    const float* output  = (const float*)d_in[0];
    const float* target  = (const float*)d_in[1];
    const float* anchors = (const float*)d_in[2];
    fused_kernel<<<NBLOCKS, 256>>>(output, target, anchors, (float*)d_out);
}